// round 9
// baseline (speedup 1.0000x reference)
#include <cuda_runtime.h>
#include <cuda_fp16.h>
#include <cstdint>

#define HW 128
#define CH 128
#define NB 8

// ---------------------------------------------------------------------------
// Device-global scratch
// ---------------------------------------------------------------------------
__device__ __align__(256) __half d_x16[(size_t)NB * HW * HW * CH];  // NHWC fp16
// Winograd weights in B-fragment order: [widx 128][wN 4][lane 32][8 u32]
// widx = (hc*16 + nu)*4 + cc   (hc = ci-half, cc = 16-ci chunk within half)
__device__ __align__(256) uint32_t d_WU[128 * 4 * 32 * 8];          // 512KB
__device__ float d_Beff[128];

__constant__ int cJ[8][8] = {
  {0,1,2,3,4,5,6,7},{1,0,4,6,2,7,3,5},{2,4,0,5,1,3,7,6},{3,6,5,0,7,2,1,4},
  {4,2,1,7,0,6,5,3},{5,7,3,2,6,0,4,1},{6,3,7,1,5,4,0,2},{7,5,6,4,3,1,2,0}};
__constant__ float cS[8][8] = {
  { 1, 1, 1, 1,-1,-1,-1,-1},{ 1, 1,-1,-1, 1,-1, 1,-1},
  { 1, 1, 1,-1,-1, 1, 1, 1},{ 1, 1, 1, 1,-1,-1,-1,-1},
  { 1, 1,-1, 1, 1, 1,-1, 1},{ 1, 1, 1,-1,-1, 1, 1, 1},
  { 1, 1,-1,-1, 1,-1, 1,-1},{ 1, 1,-1, 1, 1, 1,-1, 1}};

__device__ __forceinline__ uint32_t smem_u32(const void* p) {
  uint32_t a;
  asm("{ .reg .u64 t; cvta.to.shared.u64 t, %1; cvt.u32.u64 %0, t; }"
      : "=r"(a) : "l"(p));
  return a;
}
__device__ __forceinline__ void cp16(uint32_t dst, const void* src) {
  asm volatile("cp.async.cg.shared.global [%0], [%1], 16;"
               :: "r"(dst), "l"(src) : "memory");
}
__device__ __forceinline__ void cp_commit() {
  asm volatile("cp.async.commit_group;" ::: "memory");
}
__device__ __forceinline__ void cp_wait0() {
  asm volatile("cp.async.wait_group 0;" ::: "memory");
}

// ---------------------------------------------------------------------------
// Prepass 1: fp32 NCHW -> fp16 NHWC (unchanged).
// ---------------------------------------------------------------------------
#define S1 132
#define S2 136
#define XPREP_SMEM ((128 * S1 + 128 * S2) * 2)

__global__ void __launch_bounds__(256) xprep_kernel(const float* __restrict__ x) {
  extern __shared__ __align__(16) __half xsm[];
  __half* sm1 = xsm;
  __half* sm2 = xsm + 128 * S1;
  const int h = blockIdx.x, b = blockIdx.y, tid = threadIdx.x;
  const float* xp = x + ((size_t)b * CH) * HW * HW + (size_t)h * HW;

#pragma unroll
  for (int i = 0; i < 4; ++i) {
    int t = tid + i * 256;
    int ci = t >> 3, seg = t & 7;
    const float4* src = (const float4*)(xp + (size_t)ci * HW * HW + seg * 16);
    float4 v0 = src[0], v1 = src[1], v2 = src[2], v3 = src[3];
    __half2* dst = (__half2*)(sm1 + ci * S1 + seg * 16);
    dst[0] = __floats2half2_rn(v0.x, v0.y);
    dst[1] = __floats2half2_rn(v0.z, v0.w);
    dst[2] = __floats2half2_rn(v1.x, v1.y);
    dst[3] = __floats2half2_rn(v1.z, v1.w);
    dst[4] = __floats2half2_rn(v2.x, v2.y);
    dst[5] = __floats2half2_rn(v2.z, v2.w);
    dst[6] = __floats2half2_rn(v3.x, v3.y);
    dst[7] = __floats2half2_rn(v3.z, v3.w);
  }
  __syncthreads();

#pragma unroll
  for (int i = 0; i < 4; ++i) {
    int t = tid + i * 256;
    int w2 = (t & 7) | (((t >> 5) & 7) << 3);
    int c8 = ((t >> 3) & 3) | ((t >> 8) << 2);
    int w = w2 * 2;
    __half lo[8], hi[8];
#pragma unroll
    for (int jj = 0; jj < 8; ++jj) {
      uint32_t v = *(const uint32_t*)(sm1 + (c8 * 8 + jj) * S1 + w);
      lo[jj] = __ushort_as_half((unsigned short)(v & 0xFFFF));
      hi[jj] = __ushort_as_half((unsigned short)(v >> 16));
    }
    *(uint4*)(sm2 + (size_t)w * S2 + c8 * 8)       = *(const uint4*)lo;
    *(uint4*)(sm2 + (size_t)(w + 1) * S2 + c8 * 8) = *(const uint4*)hi;
  }
  __syncthreads();

  __half* op = d_x16 + ((size_t)(b * HW + h)) * HW * CH;
#pragma unroll
  for (int i = 0; i < 8; ++i) {
    int t = tid + i * 256;
    int c8 = t & 15;
    int w = ((t >> 4) & 1) | (((t >> 5)) << 1);
    uint4 u = *(const uint4*)(sm2 + (size_t)w * S2 + c8 * 8);
    *(uint4*)(op + (size_t)w * CH + c8 * 8) = u;
  }
}

// ---------------------------------------------------------------------------
// Prepass 2: GA3-fold + Winograd weight transform, B-fragment order; bias.
// ---------------------------------------------------------------------------
__global__ void __launch_bounds__(256)
wu_kernel(const float* __restrict__ W, const float* __restrict__ bia) {
  int t = blockIdx.x * 256 + threadIdx.x;
  if (blockIdx.x == 0 && threadIdx.x < 128) {
    int co = threadIdx.x, cout = co >> 3, m = co & 7;
    float s = 0.f;
#pragma unroll
    for (int k = 0; k < 8; k++) s += cS[m][k] * bia[cJ[m][k] * 16 + cout];
    d_Beff[co] = s;
  }
  if (t >= 128 * 64) return;
  int co = t >> 6, cp = t & 63;
  int m = co & 7, cout = co >> 3;

  float U2[2][16];
#pragma unroll
  for (int s2 = 0; s2 < 2; ++s2) {
    int ci = cp * 2 + s2;
    int cin = ci >> 3, k = ci & 7;
    float sg = cS[m][k];
    const float* wp = W + ((cJ[m][k] * 16 + cout) * 16 + cin) * 9;
    float w[3][3];
#pragma unroll
    for (int r = 0; r < 3; ++r)
#pragma unroll
      for (int c = 0; c < 3; ++c) w[r][c] = sg * wp[r * 3 + c];
    float Gw[4][3];
#pragma unroll
    for (int c = 0; c < 3; ++c) {
      Gw[0][c] = w[0][c];
      Gw[1][c] = 0.5f * (w[0][c] + w[1][c] + w[2][c]);
      Gw[2][c] = 0.5f * (w[0][c] - w[1][c] + w[2][c]);
      Gw[3][c] = w[2][c];
    }
#pragma unroll
    for (int i = 0; i < 4; ++i) {
      U2[s2][i * 4 + 0] = Gw[i][0];
      U2[s2][i * 4 + 1] = 0.5f * (Gw[i][0] + Gw[i][1] + Gw[i][2]);
      U2[s2][i * 4 + 2] = 0.5f * (Gw[i][0] - Gw[i][1] + Gw[i][2]);
      U2[s2][i * 4 + 3] = Gw[i][2];
    }
  }
  int cc8 = cp >> 3;                    // global 16-ci chunk 0..7
  int bi = (cp >> 2) & 1;
  int q = cp & 3;
  int l = (co & 7) * 4 + q;
  int wN = co >> 5;
  int f = (co >> 3) & 3;
#pragma unroll
  for (int nu = 0; nu < 16; ++nu) {
    int widx = ((cc8 >> 2) * 16 + nu) * 4 + (cc8 & 3);
    __half2 hv = __floats2half2_rn(U2[0][nu], U2[1][nu]);
    d_WU[((widx * 4 + wN) * 32 + l) * 8 + f * 2 + bi] = *(uint32_t*)&hv;
  }
}

// ---------------------------------------------------------------------------
// Winograd conv. CTA per (b, tile-row): 64 tiles x 128 co. K split into two
// 64-ci halves; per half: stage A, transform all 16 nu planes into V, then
// nu-outer / K-inner GEMM with ONE fold per nu (fold hoisted out of K loop).
// 512 threads = 16 warps (4M x 4N), warp tile m16 x n32 per nu.
// ---------------------------------------------------------------------------
#define A_SLOT 72                       // halves per (r, wslot): 144B stride
#define A_NSLOT 132
#define A_BYTES (4 * A_NSLOT * A_SLOT * 2)   // 76032
#define V_ROW 144                       // bytes per tile row in a nu plane
#define V_BYTES (16 * 64 * V_ROW)       // 147456
#define SM_TOTAL (A_BYTES + V_BYTES)    // 223488
#define NTHR 512

__global__ void __launch_bounds__(NTHR, 1)
conv_wino(float* __restrict__ out) {
  extern __shared__ __align__(128) unsigned char sh[];
  const uint32_t sA = smem_u32(sh);
  const uint32_t sV = sA + A_BYTES;

  const int tid = threadIdx.x, warp = tid >> 5, lane = tid & 31;
  const int th = blockIdx.x, b = blockIdx.y;
  const int h0 = th * 2;
  const int wM = warp >> 2, wN = warp & 3;
  const int g = lane >> 2, q = lane & 3;
  const int rsel = lane & 15, csel = lane >> 4;

  // zero A once (halo slots + invalid h rows persist as zero; the valid/
  // invalid row set is identical for both ci-halves)
  {
    uint4 z = make_uint4(0, 0, 0, 0);
    uint4* p = (uint4*)sh;
    for (int i = tid; i < A_BYTES / 16; i += NTHR) p[i] = z;
  }
  __syncthreads();

  float outacc[4][2][2][2][2];
#pragma unroll
  for (int f = 0; f < 4; ++f)
#pragma unroll
    for (int i1 = 0; i1 < 2; ++i1)
#pragma unroll
      for (int i2 = 0; i2 < 2; ++i2)
#pragma unroll
        for (int i3 = 0; i3 < 2; ++i3)
#pragma unroll
          for (int i4 = 0; i4 < 2; ++i4) outacc[f][i1][i2][i3][i4] = 0.f;

  auto issueA = [&](int hc) {
#pragma unroll
    for (int i = 0; i < 8; ++i) {
      int task = tid + i * NTHR;        // r(2) | w(7) | seg(3)
      int r = task >> 10;
      int w = (task >> 3) & 127;
      int seg = task & 7;
      int gh = h0 - 1 + r;
      if ((unsigned)gh < (unsigned)HW) {
        const __half* src = d_x16 +
            (((size_t)(b * HW + gh) * HW + w) * CH + hc * 64 + seg * 8);
        cp16(sA + ((uint32_t)(r * A_NSLOT + w + 1) * A_SLOT + seg * 8) * 2, src);
      }
    }
    cp_commit();
  };

  // Input transform: item = (tile tw, ci-pair cp=lane). All A reads and V
  // writes are conflict-free (32 consecutive words per warp).
  auto transform = [&]() {
#pragma unroll
    for (int i = 0; i < 4; ++i) {
      int tw = i * 16 + warp;
      int cp = lane;
      uint32_t abase = sA + ((uint32_t)(2 * tw) * A_SLOT + cp * 2) * 2;
      __half2 te[4][4];
#pragma unroll
      for (int j = 0; j < 4; ++j) {
        __half2 d0 = *(const __half2*)(sh + (abase - sA) + (uint32_t)((0 * A_NSLOT + j) * A_SLOT) * 2);
        __half2 d1 = *(const __half2*)(sh + (abase - sA) + (uint32_t)((1 * A_NSLOT + j) * A_SLOT) * 2);
        __half2 d2 = *(const __half2*)(sh + (abase - sA) + (uint32_t)((2 * A_NSLOT + j) * A_SLOT) * 2);
        __half2 d3 = *(const __half2*)(sh + (abase - sA) + (uint32_t)((3 * A_NSLOT + j) * A_SLOT) * 2);
        te[0][j] = __hsub2(d0, d2);
        te[1][j] = __hadd2(d1, d2);
        te[2][j] = __hsub2(d2, d1);
        te[3][j] = __hsub2(d1, d3);
      }
#pragma unroll
      for (int i2 = 0; i2 < 4; ++i2) {
        __half2 v0 = __hsub2(te[i2][0], te[i2][2]);
        __half2 v1 = __hadd2(te[i2][1], te[i2][2]);
        __half2 v2 = __hsub2(te[i2][2], te[i2][1]);
        __half2 v3 = __hsub2(te[i2][1], te[i2][3]);
        uint32_t vb = (uint32_t)(((i2 * 4) * 64 + tw) * V_ROW) + cp * 4;
        *(__half2*)(sh + A_BYTES + vb)               = v0;
        *(__half2*)(sh + A_BYTES + vb + 64 * V_ROW)  = v1;
        *(__half2*)(sh + A_BYTES + vb + 2 * 64 * V_ROW) = v2;
        *(__half2*)(sh + A_BYTES + vb + 3 * 64 * V_ROW) = v3;
      }
    }
  };

  auto ldW = [&](int widx, uint4& lo, uint4& hi) {
    const uint4* p = (const uint4*)d_WU + ((widx * 4 + wN) * 32 + lane) * 2;
    lo = p[0]; hi = p[1];
  };

  const float AT0[4] = {1.f, 1.f, 1.f, 0.f};
  const float AT1[4] = {0.f, 1.f, -1.f, -1.f};
  const float fz = 0.f;

  issueA(0);
  cp_wait0();
  __syncthreads();

#pragma unroll 1
  for (int hc = 0; hc < 2; ++hc) {
    transform();
    __syncthreads();                     // V(hc) ready; A now free
    if (hc == 0) issueA(1);              // overlap A(1) load with MMA(0)

    uint4 wlo, whi, nlo, nhi;
    ldW(hc * 64, wlo, whi);

#pragma unroll
    for (int nu = 0; nu < 16; ++nu) {
      float macc[4][4];
#pragma unroll
      for (int cc = 0; cc < 4; ++cc) {
        int widx = (hc * 16 + nu) * 4 + cc;
        int nwidx = (widx < 127) ? widx + 1 : widx;
        ldW(nwidx, nlo, nhi);

        uint32_t a0, a1, a2, a3;
        {
          uint32_t addr = sV + (uint32_t)((nu * 64 + wM * 16 + rsel) * V_ROW)
                          + cc * 32 + csel * 16;
          asm volatile(
            "ldmatrix.sync.aligned.m8n8.x4.shared.b16 {%0,%1,%2,%3}, [%4];\n"
            : "=r"(a0), "=r"(a1), "=r"(a2), "=r"(a3) : "r"(addr));
        }
        uint32_t bfr[4][2] = {
          {wlo.x, wlo.y}, {wlo.z, wlo.w}, {whi.x, whi.y}, {whi.z, whi.w}};

        if (cc == 0) {
#pragma unroll
          for (int f = 0; f < 4; ++f)
            asm volatile(
              "mma.sync.aligned.m16n8k16.row.col.f32.f16.f16.f32 "
              "{%0,%1,%2,%3}, {%4,%5,%6,%7}, {%8,%9}, {%10,%10,%10,%10};\n"
              : "=f"(macc[f][0]), "=f"(macc[f][1]),
                "=f"(macc[f][2]), "=f"(macc[f][3])
              : "r"(a0), "r"(a1), "r"(a2), "r"(a3),
                "r"(bfr[f][0]), "r"(bfr[f][1]), "f"(fz));
        } else {
#pragma unroll
          for (int f = 0; f < 4; ++f)
            asm volatile(
              "mma.sync.aligned.m16n8k16.row.col.f32.f16.f16.f32 "
              "{%0,%1,%2,%3}, {%4,%5,%6,%7}, {%8,%9}, {%0,%1,%2,%3};\n"
              : "+f"(macc[f][0]), "+f"(macc[f][1]),
                "+f"(macc[f][2]), "+f"(macc[f][3])
              : "r"(a0), "r"(a1), "r"(a2), "r"(a3),
                "r"(bfr[f][0]), "r"(bfr[f][1]));
        }
        wlo = nlo; whi = nhi;
      }

      // fold once per nu
      const int nur = nu >> 2, nuc = nu & 3;
#pragma unroll
      for (int f = 0; f < 4; ++f)
#pragma unroll
        for (int gi = 0; gi < 2; ++gi)
#pragma unroll
          for (int ji = 0; ji < 2; ++ji) {
            float mval = macc[f][gi * 2 + ji];
#pragma unroll
            for (int x = 0; x < 2; ++x) {
              float cx = (x == 0) ? AT0[nur] : AT1[nur];
              if (cx == 0.f) continue;
#pragma unroll
              for (int y = 0; y < 2; ++y) {
                float cy = (y == 0) ? AT0[nuc] : AT1[nuc];
                if (cy == 0.f) continue;
                outacc[f][gi][x][ji][y] += (cx * cy) * mval;
              }
            }
          }
    }

    if (hc == 0) {
      cp_wait0();
      __syncthreads();                   // A(1) ready AND everyone done with V(0)
    }
  }

  // ---- epilogue: bias + float2 stores ----
#pragma unroll
  for (int f = 0; f < 4; ++f) {
#pragma unroll
    for (int ji = 0; ji < 2; ++ji) {
      int co = wN * 32 + f * 8 + 2 * q + ji;
      float be = d_Beff[co];
      float* ob = out + ((size_t)(b * CH + co)) * HW * HW;
#pragma unroll
      for (int gi = 0; gi < 2; ++gi) {
        int twp = wM * 16 + g + gi * 8;
#pragma unroll
        for (int x = 0; x < 2; ++x) {
          int hrow = h0 + x;
          float2 v;
          v.x = outacc[f][gi][x][ji][0] + be;
          v.y = outacc[f][gi][x][ji][1] + be;
          *(float2*)(ob + (size_t)hrow * HW + 2 * twp) = v;
        }
      }
    }
  }
}

// ---------------------------------------------------------------------------
extern "C" void kernel_launch(void* const* d_in, const int* in_sizes, int n_in,
                              void* d_out, int out_size) {
  (void)in_sizes; (void)n_in; (void)out_size;
  const float* x = (const float*)d_in[0];
  const float* W = (const float*)d_in[1];
  const float* b = (const float*)d_in[2];
  float* out = (float*)d_out;

  cudaFuncSetAttribute(xprep_kernel,
                       cudaFuncAttributeMaxDynamicSharedMemorySize, XPREP_SMEM);
  dim3 gx(HW, NB);
  xprep_kernel<<<gx, 256, XPREP_SMEM>>>(x);
  wu_kernel<<<32, 256>>>(W, b);

  cudaFuncSetAttribute(conv_wino,
                       cudaFuncAttributeMaxDynamicSharedMemorySize, SM_TOTAL);
  dim3 grid(64, NB);   // (tile-row, b)
  conv_wino<<<grid, NTHR, SM_TOTAL>>>(out);
}